// round 2
// baseline (speedup 1.0000x reference)
#include <cuda_runtime.h>
#include <cstdint>

// Problem dims
#define B_    32
#define CIN_  32
#define COUT_ 64
#define H_    128
#define W_    128
#define HO_   126
#define WO_   126
#define MAXCN_ 64

// Folded dense kernel: [COUT][CIN][3*3]
__device__ float g_kdense[COUT_ * CIN_ * 9];

__global__ void fold_kernel(const float* __restrict__ w, const int* __restrict__ cn) {
    int idx = blockIdx.x * blockDim.x + threadIdx.x;
    if (idx >= COUT_ * CIN_ * 9) return;
    int k = idx % 9;
    int c = (idx / 9) % CIN_;
    int o = idx / (9 * CIN_);
    int n = cn[o];
    float v = 0.f;
    if (c < n)        v += w[(o * MAXCN_ + c) * 9 + k];
    if (c + 32 < n)   v += w[(o * MAXCN_ + c + 32) * 9 + k];
    g_kdense[idx] = v;
}

// ---- packed f32x2 helpers (sm_103a dual-rate fp32 path; ptxas never emits these) ----
__device__ __forceinline__ unsigned long long pack2(float lo, float hi) {
    unsigned long long r;
    asm("mov.b64 %0, {%1, %2};" : "=l"(r) : "f"(lo), "f"(hi));
    return r;
}
__device__ __forceinline__ unsigned long long fma2(unsigned long long a, unsigned long long b,
                                                   unsigned long long c) {
    unsigned long long d;
    asm("fma.rn.f32x2 %0, %1, %2, %3;" : "=l"(d) : "l"(a), "l"(b), "l"(c));
    return d;
}
__device__ __forceinline__ void unpack2(unsigned long long v, float& lo, float& hi) {
    asm("mov.b64 {%0, %1}, %2;" : "=f"(lo), "=f"(hi) : "l"(v));
}

#define SIN_STRIDE 72   // 10 rows x 72 (66 used); conflict-free for compute reads

// Block: 512 threads = 8 oc-groups x 8 ho x 8 wo-lanes.
// Each thread: 4 oc-PAIRS (f32x2) x 8 output columns (stride 8) x 1 row.
// Tile: all 64 oc x 8 ho x 64 wo for one batch image. Double-buffered smem.
__global__ __launch_bounds__(512, 1)
void conv_kernel(const float* __restrict__ x,
                 const float* __restrict__ bias,
                 float* __restrict__ out) {
    __shared__ float sIn[2][10 * SIN_STRIDE];
    __shared__ float sW[2][COUT_ * 9];

    const int tid  = threadIdx.x;
    const int og   = tid >> 6;          // 0..7  (oc group of 8) — warp-uniform
    const int ho_i = (tid >> 3) & 7;    // 0..7
    const int wo_g = tid & 7;           // 0..7

    const int wo0 = blockIdx.x * 64;    // 0 or 64
    const int ho0 = blockIdx.y * 8;     // 0..120
    const int b   = blockIdx.z;

    // ---- input staging slots (10*66 = 660 elems, <=2 per thread) ----
    const int i0 = tid;
    const int i1 = tid + 512;
    const int r0 = i0 / 66, c0 = i0 % 66;
    const int r1 = i1 / 66, c1 = i1 % 66;
    const int row0 = ho0 + r0, col0 = wo0 + c0;
    const int row1 = ho0 + r1, col1 = wo0 + c1;
    const bool st1 = (i1 < 660);
    const bool v0  = (row0 < H_) && (col0 < W_);
    const bool v1  = st1 && (row1 < H_) && (col1 < W_);
    const int goff0 = row0 * W_ + col0;
    const int goff1 = row1 * W_ + col1;
    const float* xb = x + (long)b * CIN_ * H_ * W_;

    // ---- weight staging slots (64*9 = 576 elems) ----
    const int wi0 = tid;
    const int wi1 = tid + 512;
    const bool wv1 = (wi1 < 576);

    unsigned long long acc2[4][8];
    #pragma unroll
    for (int r = 0; r < 4; ++r)
        #pragma unroll
        for (int j = 0; j < 8; ++j) acc2[r][j] = 0ull;  // (0.0f, 0.0f)

    // prefetch channel 0
    float pi0 = v0 ? __ldg(xb + goff0) : 0.f;
    float pi1 = v1 ? __ldg(xb + goff1) : 0.f;
    float pw0 = g_kdense[(wi0 / 9) * CIN_ * 9 + 0 * 9 + (wi0 % 9)];
    float pw1 = wv1 ? g_kdense[(wi1 / 9) * CIN_ * 9 + 0 * 9 + (wi1 % 9)] : 0.f;

    // stage channel 0 into buffer 0
    sIn[0][r0 * SIN_STRIDE + c0] = pi0;
    if (st1) sIn[0][r1 * SIN_STRIDE + c1] = pi1;
    sW[0][wi0] = pw0;
    if (wv1) sW[0][wi1] = pw1;
    __syncthreads();

    for (int c = 0; c < CIN_; ++c) {
        const int cur = c & 1;

        // prefetch next channel into registers (latency hidden by compute below)
        if (c < CIN_ - 1) {
            const float* xc = xb + (long)(c + 1) * (H_ * W_);
            pi0 = v0 ? __ldg(xc + goff0) : 0.f;
            pi1 = v1 ? __ldg(xc + goff1) : 0.f;
            pw0 = g_kdense[(wi0 / 9) * CIN_ * 9 + (c + 1) * 9 + (wi0 % 9)];
            if (wv1) pw1 = g_kdense[(wi1 / 9) * CIN_ * 9 + (c + 1) * 9 + (wi1 % 9)];
        }

        // compute on buf[cur]: per thread 288 FMA2 per channel
        #pragma unroll
        for (int kh = 0; kh < 3; ++kh) {
            const float* rowp = &sIn[cur][(ho_i + kh) * SIN_STRIDE + wo_g];
            const float* wbase = &sW[cur][(og * 8) * 9 + kh * 3];
            // weight pairs: (oc=2r, oc=2r+1) per kw — 12 pairs, warp-broadcast LDS
            unsigned long long wp[4][3];
            #pragma unroll
            for (int r = 0; r < 4; ++r)
                #pragma unroll
                for (int kw = 0; kw < 3; ++kw)
                    wp[r][kw] = pack2(wbase[(2 * r) * 9 + kw], wbase[(2 * r + 1) * 9 + kw]);

            #pragma unroll
            for (int j = 0; j < 8; ++j) {
                float a0 = rowp[8 * j];
                float a1 = rowp[8 * j + 1];
                float a2 = rowp[8 * j + 2];
                unsigned long long a0d = pack2(a0, a0);
                unsigned long long a1d = pack2(a1, a1);
                unsigned long long a2d = pack2(a2, a2);
                #pragma unroll
                for (int r = 0; r < 4; ++r) {
                    unsigned long long t = acc2[r][j];
                    t = fma2(wp[r][0], a0d, t);
                    t = fma2(wp[r][1], a1d, t);
                    t = fma2(wp[r][2], a2d, t);
                    acc2[r][j] = t;
                }
            }
        }

        // stage next channel into the other buffer, one barrier per iteration
        if (c < CIN_ - 1) {
            const int nxt = cur ^ 1;
            sIn[nxt][r0 * SIN_STRIDE + c0] = pi0;
            if (st1) sIn[nxt][r1 * SIN_STRIDE + c1] = pi1;
            sW[nxt][wi0] = pw0;
            if (wv1) sW[nxt][wi1] = pw1;
            __syncthreads();
        }
    }

    // epilogue: add bias, store (coalesced: lanes wo_g consecutive columns)
    const int ho = ho0 + ho_i;
    if (ho < HO_) {
        #pragma unroll
        for (int r = 0; r < 4; ++r) {
            const int ocA = og * 8 + 2 * r;
            const int ocB = ocA + 1;
            const float* bpA = bias + ((long)ocA * HO_ + ho) * WO_;
            const float* bpB = bias + ((long)ocB * HO_ + ho) * WO_;
            float* opA = out + (((long)b * COUT_ + ocA) * HO_ + ho) * WO_;
            float* opB = out + (((long)b * COUT_ + ocB) * HO_ + ho) * WO_;
            #pragma unroll
            for (int j = 0; j < 8; ++j) {
                const int wo = wo0 + wo_g + 8 * j;
                if (wo < WO_) {
                    float lo, hi;
                    unpack2(acc2[r][j], lo, hi);
                    opA[wo] = lo + __ldg(bpA + wo);
                    opB[wo] = hi + __ldg(bpB + wo);
                }
            }
        }
    }
}

extern "C" void kernel_launch(void* const* d_in, const int* in_sizes, int n_in,
                              void* d_out, int out_size) {
    const float* x    = (const float*)d_in[0];   // [32,32,128,128]
    const float* w    = (const float*)d_in[1];   // [64,64,3,3]
    const float* bias = (const float*)d_in[2];   // [64,126,126]
    const int*   cn   = (const int*)d_in[3];     // [64]
    float* out = (float*)d_out;                  // [32,64,126,126]

    fold_kernel<<<(COUT_ * CIN_ * 9 + 255) / 256, 256>>>(w, cn);
    conv_kernel<<<dim3(2, 16, 32), 512>>>(x, bias, out);
}